// round 12
// baseline (speedup 1.0000x reference)
#include <cuda_runtime.h>
#include <math.h>

#define NTOK 65536
#define CODES_OFF 33554432
#define LAT_OFF   34144256
#define COMMIT_OFF 38862848

// ---------------- device scratch (no allocation) ----------------
__device__ float g_P[72 * NTOK];      // [q][tok], q = i*8+d
__device__ float g_Q[72 * NTOK];      // selected raw code vecs, [q][tok]
__device__ float g_pr[9 * NTOK * 8];  // normalized probs per (stage, tok)
__device__ float g_WinT[512 * 72];    // [c][q]
__device__ float g_WoT[512 * 72];     // [c][q]
__device__ float g_M[81 * 64];        // M[i][j][d][e]
__device__ float g_cvec[81 * 8];      // W_in_i @ out_b_j
__device__ float g_Cbias[512];        // sum_j out_b_j
__device__ float g_cbn[9 * 8 * 128 * 8];  // normalized codebooks
__device__ float g_cn[9 * 8 * 128];       // raw norms
__device__ float g_cnt[72];
__device__ float g_ps[72];
__device__ float g_commit[1];

// ---------------- packed f32x2 helpers ----------------
__device__ __forceinline__ unsigned long long pack2(float lo, float hi) {
    unsigned long long r;
    asm("mov.b64 %0, {%1,%2};" : "=l"(r) : "f"(lo), "f"(hi));
    return r;
}
__device__ __forceinline__ void unpack2(unsigned long long v, float& lo, float& hi) {
    asm("mov.b64 {%0,%1}, %2;" : "=f"(lo), "=f"(hi) : "l"(v));
}
__device__ __forceinline__ unsigned long long fma2(unsigned long long a,
                                                   unsigned long long b,
                                                   unsigned long long c) {
    unsigned long long r;
    asm("fma.rn.f32x2 %0, %1, %2, %3;" : "=l"(r) : "l"(a), "l"(b), "l"(c));
    return r;
}
__device__ __forceinline__ unsigned long long add2(unsigned long long a,
                                                   unsigned long long b) {
    unsigned long long r;
    asm("add.rn.f32x2 %0, %1, %2;" : "=l"(r) : "l"(a), "l"(b));
    return r;
}

// ================================================================
// prep1: weight-norm weights (transposed), codebook norms, Cbias, zeros
// ================================================================
__global__ void prep1_kernel(const float* __restrict__ in_v, const float* __restrict__ in_g,
                             const float* __restrict__ out_v, const float* __restrict__ out_g,
                             const float* __restrict__ out_b, const float* __restrict__ cb) {
    int tid = blockIdx.x * blockDim.x + threadIdx.x;
    if (tid < 72) {
        const float* v = in_v + (size_t)tid * 512;
        float s = 0.f;
        for (int c = 0; c < 512; c++) s = fmaf(v[c], v[c], s);
        float inv = in_g[tid] / sqrtf(s);
        for (int c = 0; c < 512; c++) g_WinT[c * 72 + tid] = v[c] * inv;
    } else if (tid < 72 + 4608) {
        int rid = tid - 72;                       // j*512 + c
        int j = rid >> 9, c = rid & 511;
        const float* v = out_v + (size_t)rid * 8;
        float s = 0.f;
#pragma unroll
        for (int d = 0; d < 8; d++) s = fmaf(v[d], v[d], s);
        float inv = out_g[rid] / sqrtf(s);
#pragma unroll
        for (int d = 0; d < 8; d++) g_WoT[c * 72 + j * 8 + d] = v[d] * inv;
    } else if (tid < 4680 + 512) {
        int c = tid - 4680;
        float s = 0.f;
        for (int j = 0; j < 9; j++) s += out_b[j * 512 + c];
        g_Cbias[c] = s;
    } else if (tid < 5192 + 9216) {
        int rid = tid - 5192;                     // i*1024 + e*128 + k
        const float* v = cb + (size_t)rid * 8;
        float s = 0.f;
#pragma unroll
        for (int d = 0; d < 8; d++) s = fmaf(v[d], v[d], s);
        float rawn = sqrtf(s);
        float m = fmaxf(rawn, 1e-12f);
#pragma unroll
        for (int d = 0; d < 8; d++) g_cbn[rid * 8 + d] = v[d] / m;
        g_cn[rid] = rawn;
    } else if (tid < 14408 + 145) {
        int r = tid - 14408;
        if (r < 72) g_cnt[r] = 0.f;
        else if (r < 144) g_ps[r - 72] = 0.f;
        else g_commit[0] = 0.f;
    }
}

// ================================================================
// prep2: M[i][j] = W_in_i @ W_out_j, cvec[i][j] = W_in_i @ out_b_j
// ================================================================
__global__ void prep2_kernel(const float* __restrict__ out_b) {
    int ij = blockIdx.x;              // i*9+j
    int i = ij / 9, j = ij % 9;
    int tid = threadIdx.x;            // 72 threads
    if (tid < 64) {
        int d = tid >> 3, e = tid & 7;
        float s = 0.f;
        for (int c = 0; c < 512; c++)
            s = fmaf(g_WinT[c * 72 + i * 8 + d], g_WoT[c * 72 + j * 8 + e], s);
        g_M[ij * 64 + d * 8 + e] = s;
    } else {
        int d = tid - 64;
        float s = 0.f;
        for (int c = 0; c < 512; c++)
            s = fmaf(g_WinT[c * 72 + i * 8 + d], out_b[j * 512 + c], s);
        g_cvec[ij * 8 + d] = s;
    }
}

// pad kernel: positions kA as the 4th launch so ncu's capture window hits it
__global__ void pad_kernel() {}

// ================================================================
// kernel A: P = W_in_all @ z + in_b.
// grid 192: 3 q-groups (24 q each) x 64 token-tiles (1024 tokens).
// Thread: 4 adjacent tokens x 12 q-pairs = 48 packed accumulators.
// Per c: 6 LDS.128 feed 48 fma2 (8:1). smem 48KB -> 2 blocks/SM, 1 wave.
// ================================================================
__global__ __launch_bounds__(256, 2) void kA_kernel(const float* __restrict__ z,
                                                    const float* __restrict__ in_b) {
    extern __shared__ float ws[];     // 512*24 floats
    int tid = threadIdx.x;
    int qg = blockIdx.x >> 6;         // 0..2
    int tile = blockIdx.x & 63;

    // stage q-group weights: ws[c*24 + j] = g_WinT[c*72 + qg*24 + j]
#pragma unroll
    for (int u = 0; u < 12; u++) {
        int g = tid + u * 256;        // 3072 float4
        int c = g / 6, f = g % 6;
        ((float4*)ws)[c * 6 + f] = *(const float4*)(g_WinT + c * 72 + qg * 24 + f * 4);
    }
    __syncthreads();

    int tok0 = tile * 1024 + 4 * tid;
    int b = tok0 >> 12, t0 = tok0 & 4095;

    unsigned long long acc[12][4];
#pragma unroll
    for (int p = 0; p < 12; p++)
#pragma unroll
        for (int t = 0; t < 4; t++) acc[p][t] = 0ULL;

    const float* zp = z + (size_t)b * 512 * 4096 + t0;
#pragma unroll 1
    for (int c0 = 0; c0 < 512; c0 += 2) {
        float4 z0 = *(const float4*)(zp + (size_t)c0 * 4096);
        float4 z1 = *(const float4*)(zp + (size_t)(c0 + 1) * 4096);
#pragma unroll
        for (int cc = 0; cc < 2; cc++) {
            float4 zv = cc ? z1 : z0;
            unsigned long long z2[4] = { pack2(zv.x, zv.x), pack2(zv.y, zv.y),
                                         pack2(zv.z, zv.z), pack2(zv.w, zv.w) };
            const ulonglong2* wrow = (const ulonglong2*)(ws + (c0 + cc) * 24);
#pragma unroll
            for (int u = 0; u < 6; u++) {
                ulonglong2 w = wrow[u];
#pragma unroll
                for (int t = 0; t < 4; t++) {
                    acc[2 * u][t]     = fma2(w.x, z2[t], acc[2 * u][t]);
                    acc[2 * u + 1][t] = fma2(w.y, z2[t], acc[2 * u + 1][t]);
                }
            }
        }
    }
#pragma unroll
    for (int p = 0; p < 12; p++) {
        int q = qg * 24 + 2 * p;
        float lo[4], hi[4];
#pragma unroll
        for (int t = 0; t < 4; t++) unpack2(acc[p][t], lo[t], hi[t]);
        float be = __ldg(&in_b[q]), bo = __ldg(&in_b[q + 1]);
        *(float4*)&g_P[(size_t)q * NTOK + tok0] =
            make_float4(lo[0] + be, lo[1] + be, lo[2] + be, lo[3] + be);
        *(float4*)&g_P[(size_t)(q + 1) * NTOK + tok0] =
            make_float4(hi[0] + bo, hi[1] + bo, hi[2] + bo, hi[3] + bo);
    }
}

// ================================================================
// kernel B: per-token sequential RVQ, 1 thread/token, stages unrolled,
// q history in registers. grid 256 x 256.
// ================================================================
__global__ __launch_bounds__(256, 2) void kB_kernel(const float* __restrict__ r_w1,
                                                    const float* __restrict__ r_b1,
                                                    const float* __restrict__ r_w2,
                                                    const float* __restrict__ r_b2,
                                                    float* __restrict__ out) {
    extern __shared__ float4 sm4[];
    float4* s_cb = sm4;                       // 2056 float4 (expert stride 1028 floats)
    float* fb = (float*)(sm4 + 2056);
    float* s_M    = fb;                       // 5184
    float* s_cvec = s_M + 5184;               // 648
    float* s_w1   = s_cvec + 648;             // 576
    float* s_b1   = s_w1 + 576;               // 72
    float* s_w2   = s_b1 + 72;                // 576
    float* s_b2   = s_w2 + 576;               // 72
    float* s_red  = s_b2 + 72;                // 8

    int tid = threadIdx.x, lane = tid & 31, wid = tid >> 5;
    int tok = blockIdx.x * 256 + tid;
    int b = tok >> 12, t = tok & 4095;

    // one-time staging (ordered by the stage-0 barrier below)
    for (int j = tid; j < 5184; j += 256) s_M[j] = g_M[j];
    for (int j = tid; j < 648; j += 256) s_cvec[j] = g_cvec[j];
    for (int j = tid; j < 576; j += 256) { s_w1[j] = r_w1[j]; s_w2[j] = r_w2[j]; }
    if (tid < 72) { s_b1[tid] = r_b1[tid]; s_b2[tid] = r_b2[tid]; }

    float q_hist[72];
    float commit_loc = 0.f;
    float* out_codes = out + CODES_OFF;
    float* out_lat = out + LAT_OFF;

#pragma unroll
    for (int i = 0; i < 9; i++) {
        __syncthreads();
        {   // stage codebook into padded smem
            const float4* src = (const float4*)(g_cbn + (size_t)i * 8192);
#pragma unroll
            for (int j = 0; j < 8; j++) {
                int g = tid + j * 256;
                int e = g >> 8, r = g & 255;
                s_cb[e * 257 + r] = src[g];
            }
        }
        __syncthreads();

        // z_e = P_i - sum_{j<i} (M_ij q_j + c_ij), q from registers
        float ze[8];
#pragma unroll
        for (int d = 0; d < 8; d++) ze[d] = g_P[(size_t)(i * 8 + d) * NTOK + tok];
#pragma unroll
        for (int j = 0; j < i; j++) {
            const float* Mij = s_M + (i * 9 + j) * 64;
            const float* cij = s_cvec + (i * 9 + j) * 8;
#pragma unroll
            for (int d = 0; d < 8; d++) {
                float s = cij[d];
#pragma unroll
                for (int e = 0; e < 8; e++) s = fmaf(Mij[d * 8 + e], q_hist[j * 8 + e], s);
                ze[d] -= s;
            }
        }

        // latents output
        {
            float4* lp = (float4*)(out_lat + ((size_t)((b * 9 + i) * 4096 + t)) * 8);
            lp[0] = make_float4(ze[0], ze[1], ze[2], ze[3]);
            lp[1] = make_float4(ze[4], ze[5], ze[6], ze[7]);
        }

        // router (weights in smem, broadcast)
        float h[8];
#pragma unroll
        for (int hh = 0; hh < 8; hh++) {
            float s = s_b1[i * 8 + hh];
#pragma unroll
            for (int d = 0; d < 8; d++) s = fmaf(s_w1[(i * 8 + hh) * 8 + d], ze[d], s);
            h[hh] = fmaxf(s, 0.f);
        }
        float lg[8];
        float lmax = -3.4e38f;
        int estar = 0;
#pragma unroll
        for (int e = 0; e < 8; e++) {
            float s = s_b2[i * 8 + e];
#pragma unroll
            for (int hh = 0; hh < 8; hh++) s = fmaf(s_w2[(i * 8 + e) * 8 + hh], h[hh], s);
            lg[e] = s;
            if (s > lmax) { lmax = s; estar = e; }
        }

        // normalized probs -> global (aux loss computed by kR)
        float pr[8], psum = 0.f;
#pragma unroll
        for (int e = 0; e < 8; e++) { pr[e] = expf(lg[e] - lmax); psum += pr[e]; }
        float pinv = 1.f / psum;
        {
            float4* pp = (float4*)(g_pr + ((size_t)i * NTOK + tok) * 8);
            pp[0] = make_float4(pr[0] * pinv, pr[1] * pinv, pr[2] * pinv, pr[3] * pinv);
            pp[1] = make_float4(pr[4] * pinv, pr[5] * pinv, pr[6] * pinv, pr[7] * pinv);
        }

        // nearest neighbor: argmax_k ze . cbn_k  (|cbn|=1, scale-invariant)
        const float4* cpe = s_cb + estar * 257;
        float best = -3.4e38f;
        int bk = 0;
#pragma unroll 4
        for (int k = 0; k < 128; k++) {
            float4 a = cpe[2 * k], c = cpe[2 * k + 1];
            float dt = fmaf(ze[0], a.x, fmaf(ze[1], a.y, fmaf(ze[2], a.z, ze[3] * a.w)));
            dt = fmaf(ze[4], c.x, fmaf(ze[5], c.y, fmaf(ze[6], c.z, fmaf(ze[7], c.w, dt))));
            if (dt > best) { best = dt; bk = k; }
        }

        float cn = __ldg(&g_cn[i * 1024 + estar * 128 + bk]);
        float4 a = cpe[2 * bk], c = cpe[2 * bk + 1];
        float q[8] = { a.x * cn, a.y * cn, a.z * cn, a.w * cn,
                       c.x * cn, c.y * cn, c.z * cn, c.w * cn };
#pragma unroll
        for (int d = 0; d < 8; d++) {
            q_hist[i * 8 + d] = q[d];
            g_Q[(size_t)(i * 8 + d) * NTOK + tok] = q[d];
            float df = ze[d] - q[d];
            commit_loc = fmaf(df, df, commit_loc);
        }
        out_codes[(size_t)(b * 9 + i) * 4096 + t] = (float)(bk + 128 * estar);
    }

    // reduce commitment
    commit_loc += __shfl_xor_sync(0xffffffffu, commit_loc, 16);
    commit_loc += __shfl_xor_sync(0xffffffffu, commit_loc, 8);
    commit_loc += __shfl_xor_sync(0xffffffffu, commit_loc, 4);
    commit_loc += __shfl_xor_sync(0xffffffffu, commit_loc, 2);
    commit_loc += __shfl_xor_sync(0xffffffffu, commit_loc, 1);
    __syncthreads();
    if (lane == 0) s_red[wid] = commit_loc;
    __syncthreads();
    if (tid == 0) {
        float s = 0.f;
        for (int w = 0; w < 8; w++) s += s_red[w];
        atomicAdd(&g_commit[0], s);
    }
}

// ================================================================
// kernel R: reduce g_pr -> per-(stage,expert) prob sums + argmax counts
// ================================================================
__global__ void kR_kernel() {
    int i = blockIdx.x >> 5, chunk = blockIdx.x & 31;
    int tid = threadIdx.x, lane = tid & 31;
    float ps[8] = {0, 0, 0, 0, 0, 0, 0, 0};
    float cnt[8] = {0, 0, 0, 0, 0, 0, 0, 0};
    const float4* base = (const float4*)(g_pr + (size_t)i * NTOK * 8);
    int tok0 = chunk * 2048 + tid * 8;
#pragma unroll
    for (int u = 0; u < 8; u++) {
        int tok = tok0 + u;
        float4 v0 = base[tok * 2], v1 = base[tok * 2 + 1];
        float v[8] = {v0.x, v0.y, v0.z, v0.w, v1.x, v1.y, v1.z, v1.w};
        int am = 0;
        float m = v[0];
#pragma unroll
        for (int e = 1; e < 8; e++) if (v[e] > m) { m = v[e]; am = e; }
#pragma unroll
        for (int e = 0; e < 8; e++) {
            ps[e] += v[e];
            cnt[e] += (am == e) ? 1.f : 0.f;
        }
    }
#pragma unroll
    for (int e = 0; e < 8; e++) {
        for (int s = 16; s; s >>= 1) {
            ps[e] += __shfl_xor_sync(0xffffffffu, ps[e], s);
            cnt[e] += __shfl_xor_sync(0xffffffffu, cnt[e], s);
        }
    }
    if (lane == 0) {
#pragma unroll
        for (int e = 0; e < 8; e++) {
            atomicAdd(&g_ps[i * 8 + e], ps[e]);
            atomicAdd(&g_cnt[i * 8 + e], cnt[e]);
        }
    }
}

// ================================================================
// kernel C: z_q = W_out_cat @ Q + Cbias.
// grid 256: block = (token tile of 512) x (c-half of 256).
// Thread: 2 tokens sequentially, q2[36] packed regs reused.
// smem: 256x72 weights + 256 bias, staged ONCE per block. 0.86 waves.
// ================================================================
__global__ __launch_bounds__(256) void kC_kernel(float* __restrict__ out) {
    extern __shared__ float sm[];          // 256*72 + 256 floats
    float* ws = sm;
    float* cbias = sm + 256 * 72;
    int tid = threadIdx.x;
    int ch = blockIdx.x & 1;
    int tokBase = (blockIdx.x >> 1) * 512;
    int cbase = ch * 256;

    for (int g = tid; g < 256 * 18; g += 256) {
        int cr = g / 18, j4 = g % 18;
        ((float4*)ws)[cr * 18 + j4] = *(const float4*)(g_WoT + (size_t)(cbase + cr) * 72 + j4 * 4);
    }
    if (tid < 256) cbias[tid] = g_Cbias[cbase + tid];
    __syncthreads();

#pragma unroll 1
    for (int rep = 0; rep < 2; rep++) {
        int tok = tokBase + rep * 256 + tid;
        int b = tok >> 12, t = tok & 4095;

        unsigned long long q2[36];
#pragma unroll
        for (int m = 0; m < 36; m++)
            q2[m] = pack2(g_Q[(size_t)(2 * m) * NTOK + tok],
                          g_Q[(size_t)(2 * m + 1) * NTOK + tok]);

        float* op = out + (size_t)b * 512 * 4096 + (size_t)cbase * 4096 + t;
#pragma unroll 2
        for (int cr = 0; cr < 256; cr++) {
            const ulonglong2* wr = (const ulonglong2*)(ws + cr * 72);
            unsigned long long ac0 = 0ULL, ac1 = 0ULL, ac2 = 0ULL, ac3 = 0ULL;
#pragma unroll
            for (int m = 0; m < 9; m++) {
                ulonglong2 w0 = wr[2 * m];
                ulonglong2 w1 = wr[2 * m + 1];
                ac0 = fma2(w0.x, q2[4 * m], ac0);
                ac1 = fma2(w0.y, q2[4 * m + 1], ac1);
                ac2 = fma2(w1.x, q2[4 * m + 2], ac2);
                ac3 = fma2(w1.y, q2[4 * m + 3], ac3);
            }
            unsigned long long s = add2(add2(ac0, ac1), add2(ac2, ac3));
            float lo, hi;
            unpack2(s, lo, hi);
            op[(size_t)cr * 4096] = lo + hi + cbias[cr];
        }
    }
}

// ================================================================
// final: losses
// ================================================================
__global__ void kF_kernel(float* __restrict__ out) {
    __shared__ float sa[72];
    int tid = threadIdx.x;
    if (tid < 72) sa[tid] = g_cnt[tid] * g_ps[tid];
    __syncthreads();
    if (tid == 0) {
        float aux = 0.f;
        for (int q = 0; q < 72; q++) aux += sa[q];
        aux *= (1.f / 65536.f) * (1.f / 65536.f);
        float cm = g_commit[0] / 524288.f;    // /(16*4096*8)
        out[COMMIT_OFF] = cm;
        out[COMMIT_OFF + 1] = cm;             // codebook_loss == commitment_loss numerically
        out[COMMIT_OFF + 2] = aux;
    }
}

// ================================================================
extern "C" void kernel_launch(void* const* d_in, const int* in_sizes, int n_in,
                              void* d_out, int out_size) {
    const float* z     = (const float*)d_in[0];
    const float* in_v  = (const float*)d_in[1];
    const float* in_g  = (const float*)d_in[2];
    const float* in_b  = (const float*)d_in[3];
    const float* out_v = (const float*)d_in[4];
    const float* out_g = (const float*)d_in[5];
    const float* out_b = (const float*)d_in[6];
    const float* r_w1  = (const float*)d_in[7];
    const float* r_b1  = (const float*)d_in[8];
    const float* r_w2  = (const float*)d_in[9];
    const float* r_b2  = (const float*)d_in[10];
    const float* cb    = (const float*)d_in[11];
    float* out = (float*)d_out;

    cudaFuncSetAttribute(kA_kernel, cudaFuncAttributeMaxDynamicSharedMemorySize, 49152);
    cudaFuncSetAttribute(kB_kernel, cudaFuncAttributeMaxDynamicSharedMemorySize, 61440);
    cudaFuncSetAttribute(kC_kernel, cudaFuncAttributeMaxDynamicSharedMemorySize, 74752);

    prep1_kernel<<<57, 256>>>(in_v, in_g, out_v, out_g, out_b, cb);
    prep2_kernel<<<81, 72>>>(out_b);
    pad_kernel<<<1, 32>>>();                 // positions kA as launch #4 for ncu capture
    kA_kernel<<<192, 256, 49152>>>(z, in_b);
    kB_kernel<<<256, 256, 61440>>>(r_w1, r_b1, r_w2, r_b2, out);
    kR_kernel<<<288, 256>>>();
    kC_kernel<<<256, 256, 74752>>>(out);
    kF_kernel<<<1, 128>>>(out);
}